// round 14
// baseline (speedup 1.0000x reference)
#include <cuda_runtime.h>
#include <cuda_bf16.h>
#include <cstdint>
#include <string.h>
#include <math.h>

#define BSZ 4096
#define DIM 256
#define NF  12288            // 3 * BSZ rows: [A ; P0 ; P1]
#define MARGIN 1.0f
#define EPSQ 1e-12f
#define ASTRIDE 40           // smem row stride in bf16 (80 B -> conflict-free ldmatrix)

#define BM 256
#define BN 128
#define ABYTES (BM * ASTRIDE * 2)      // 20480
#define BBYTES (BN * ASTRIDE * 2)      // 10240
#define STAGEBYTES (ABYTES + BBYTES)   // 30720
#define NSTAGE 3
#define SMEM_DYN (NSTAGE * STAGEBYTES + 512)

// ---------------- scratch (__device__ globals; no allocs allowed) -----------
__device__ __nv_bfloat16 g_Fh[NF * DIM];   // normalized rows, bf16 (GEMM)
__device__ float         g_pos[2 * BSZ];   // exact fp32 dot(a_i, p_{i,v})
__device__ unsigned      g_maxkey[3 * BSZ];

__device__ __forceinline__ uint32_t smem_to_u32(const void* p) {
    uint32_t a;
    asm("{ .reg .u64 t; cvta.to.shared.u64 t, %1; cvt.u32.u64 %0, t; }" : "=r"(a) : "l"(p));
    return a;
}
__device__ __forceinline__ void cp_async16(uint32_t saddr, const void* gaddr) {
    asm volatile("cp.async.ca.shared.global [%0], [%1], 16;"
                 :: "r"(saddr), "l"(gaddr) : "memory");
}
#define CP_COMMIT()  asm volatile("cp.async.commit_group;" ::: "memory")
#define CP_WAIT(n)   asm volatile("cp.async.wait_group %0;" :: "n"(n) : "memory")

// pack two floats -> bf16x2 bits
__device__ __forceinline__ uint32_t pack_bf16x2(float lo, float hi) {
    __nv_bfloat162 h = __floats2bfloat162_rn(lo, hi);
    uint32_t u;
    memcpy(&u, &h, 4);
    return u;
}

// ---- monotone float <-> uint encoding (atomicMax over signed floats) -------
__device__ __forceinline__ unsigned enc_key(float f) {
    unsigned b = __float_as_uint(f);
    return (b & 0x80000000u) ? ~b : (b | 0x80000000u);
}
__device__ __forceinline__ float dec_key(unsigned k) {
    unsigned b = (k & 0x80000000u) ? (k & 0x7fffffffu) : ~k;
    return __uint_as_float(b);
}

// ============================================================================
// Kernel 1: warp-per-row normalize (no block barriers).
// ============================================================================
__global__ __launch_bounds__(256) void normalize_kernel(
    const float* __restrict__ anchor, const float* __restrict__ positive) {
    int gw   = (blockIdx.x * 256 + threadIdx.x) >> 5;   // row 0..4095
    int lane = threadIdx.x & 31;

    const float4* a4 = (const float4*)(anchor + (size_t)gw * DIM);
    float4 a0 = a4[lane * 2], a1 = a4[lane * 2 + 1];
    float ss = a0.x*a0.x + a0.y*a0.y + a0.z*a0.z + a0.w*a0.w
             + a1.x*a1.x + a1.y*a1.y + a1.z*a1.z + a1.w*a1.w;
    #pragma unroll
    for (int o = 16; o; o >>= 1) ss += __shfl_xor_sync(0xffffffffu, ss, o);
    float inv = 1.0f / fmaxf(sqrtf(ss), 1e-12f);
    a0.x *= inv; a0.y *= inv; a0.z *= inv; a0.w *= inv;
    a1.x *= inv; a1.y *= inv; a1.z *= inv; a1.w *= inv;
    {
        uint4 o;
        o.x = pack_bf16x2(a0.x, a0.y);
        o.y = pack_bf16x2(a0.z, a0.w);
        o.z = pack_bf16x2(a1.x, a1.y);
        o.w = pack_bf16x2(a1.z, a1.w);
        ((uint4*)(g_Fh + (size_t)gw * DIM))[lane] = o;
    }

    #pragma unroll
    for (int v = 0; v < 2; v++) {
        const float4* p4 = (const float4*)(positive + ((size_t)gw * 2 + v) * DIM);
        float4 p0 = p4[lane * 2], p1 = p4[lane * 2 + 1];
        float ps = p0.x*p0.x + p0.y*p0.y + p0.z*p0.z + p0.w*p0.w
                 + p1.x*p1.x + p1.y*p1.y + p1.z*p1.z + p1.w*p1.w;
        #pragma unroll
        for (int o = 16; o; o >>= 1) ps += __shfl_xor_sync(0xffffffffu, ps, o);
        float pinv = 1.0f / fmaxf(sqrtf(ps), 1e-12f);
        p0.x *= pinv; p0.y *= pinv; p0.z *= pinv; p0.w *= pinv;
        p1.x *= pinv; p1.y *= pinv; p1.z *= pinv; p1.w *= pinv;
        uint4 o;
        o.x = pack_bf16x2(p0.x, p0.y);
        o.y = pack_bf16x2(p0.z, p0.w);
        o.z = pack_bf16x2(p1.x, p1.y);
        o.w = pack_bf16x2(p1.z, p1.w);
        ((uint4*)(g_Fh + ((size_t)(1 + v) * BSZ + gw) * DIM))[lane] = o;

        float pd = a0.x*p0.x + a0.y*p0.y + a0.z*p0.z + a0.w*p0.w
                 + a1.x*p1.x + a1.y*p1.y + a1.z*p1.z + a1.w*p1.w;
        #pragma unroll
        for (int o2 = 16; o2; o2 >>= 1) pd += __shfl_xor_sync(0xffffffffu, pd, o2);
        if (lane == 0) g_pos[v * BSZ + gw] = pd;
    }
    if (lane < 3) g_maxkey[lane * BSZ + gw] = enc_key(-2.0f);
}

// ============================================================================
// Kernel 2: bf16 mma GEMM, CTA tile 256x128, 512 threads (16 warps: 8M x 2N),
// 3-stage cp.async pipeline, one barrier per k-iter, fused masked row-max.
// Warp tile 32x64 = 2x8 mma fragments (identical to validated R12/R13 core).
// ============================================================================
__global__ __launch_bounds__(512) void gemm_max_mma(const int* __restrict__ labels) {
    extern __shared__ char dsm[];
    uint32_t sbase = smem_to_u32(dsm);
    int* clab = (int*)(dsm + NSTAGE * STAGEBYTES);

    int tid = threadIdx.x, lane = tid & 31, wid = tid >> 5;
    int rowBase = blockIdx.y * BM;     // [0, 4096)
    int colBase = blockIdx.x * BN;     // [0, 12288)
    if (tid < BN) clab[tid] = labels[(colBase & (BSZ - 1)) + tid];

    int warpM = wid & 7;               // 8 warps along M (32 rows each)
    int warpN = wid >> 3;              // 2 warps along N (64 cols each)

    // ldmatrix lane offsets (bytes, within one operand); += 32 B per k-step
    uint32_t offA[2], offB[4];
    #pragma unroll
    for (int mt = 0; mt < 2; mt++) {
        int r  = warpM * 32 + mt * 16 + (lane & 15);
        int kc = (lane >> 4) * 8;
        offA[mt] = (uint32_t)(r * ASTRIDE + kc) * 2u;
    }
    #pragma unroll
    for (int np = 0; np < 4; np++) {
        int n  = warpN * 64 + np * 16 + (lane & 7) + ((lane & 16) >> 1);
        int kc = ((lane >> 3) & 1) * 8;
        offB[np] = (uint32_t)(n * ASTRIDE + kc) * 2u;
    }

    float acc[2][8][4];
    #pragma unroll
    for (int mt = 0; mt < 2; mt++)
        #pragma unroll
        for (int nt = 0; nt < 8; nt++)
            #pragma unroll
            for (int c = 0; c < 4; c++) acc[mt][nt][c] = 0.0f;

    // Loader: 512 threads cover 128 rows x 32 bf16 (4x16B) per pass.
    int ldrow = tid >> 2, ldg = (tid & 3) * 8;
    const __nv_bfloat16* gA = g_Fh + (size_t)(rowBase + ldrow) * DIM + ldg;
    const __nv_bfloat16* gB = g_Fh + (size_t)(colBase + ldrow) * DIM + ldg;
    uint32_t srow = (uint32_t)(ldrow * ASTRIDE + ldg) * 2u;

    auto issue = [&](int stg, int kt) {
        uint32_t so = sbase + (uint32_t)stg * STAGEBYTES;
        #pragma unroll
        for (int p = 0; p < 2; p++)     // A: 2 passes of 128 rows
            cp_async16(so + (uint32_t)(p * 128 * ASTRIDE * 2) + srow,
                       gA + (size_t)p * 128 * DIM + kt);
        cp_async16(so + ABYTES + srow, gB + kt);   // B: 1 pass
    };

    issue(0, 0);  CP_COMMIT();
    issue(1, 32); CP_COMMIT();

    #pragma unroll
    for (int i = 0; i < 8; i++) {
        if (i < 7) { CP_WAIT(1); } else { CP_WAIT(0); }
        __syncthreads();                  // stage i ready; stage (i+2)%3 free
        if (i < 6) { issue((i + 2) % NSTAGE, (i + 2) * 32); CP_COMMIT(); }

        uint32_t sa = sbase + (uint32_t)(i % NSTAGE) * STAGEBYTES;
        uint32_t sb = sa + ABYTES;
        #pragma unroll
        for (int ks = 0; ks < 2; ks++) {
            uint32_t a[2][4], b[4][4];
            #pragma unroll
            for (int mt = 0; mt < 2; mt++)
                asm volatile("ldmatrix.sync.aligned.m8n8.x4.shared.b16 "
                             "{%0,%1,%2,%3}, [%4];"
                             : "=r"(a[mt][0]), "=r"(a[mt][1]),
                               "=r"(a[mt][2]), "=r"(a[mt][3])
                             : "r"(sa + offA[mt] + ks * 32u));
            #pragma unroll
            for (int np = 0; np < 4; np++)
                asm volatile("ldmatrix.sync.aligned.m8n8.x4.shared.b16 "
                             "{%0,%1,%2,%3}, [%4];"
                             : "=r"(b[np][0]), "=r"(b[np][1]),
                               "=r"(b[np][2]), "=r"(b[np][3])
                             : "r"(sb + offB[np] + ks * 32u));
            #pragma unroll
            for (int mt = 0; mt < 2; mt++)
                #pragma unroll
                for (int nt = 0; nt < 8; nt++) {
                    uint32_t b0 = b[nt >> 1][(nt & 1) * 2];
                    uint32_t b1 = b[nt >> 1][(nt & 1) * 2 + 1];
                    asm volatile(
                        "mma.sync.aligned.m16n8k16.row.col.f32.bf16.bf16.f32 "
                        "{%0,%1,%2,%3}, {%4,%5,%6,%7}, {%8,%9}, {%0,%1,%2,%3};"
                        : "+f"(acc[mt][nt][0]), "+f"(acc[mt][nt][1]),
                          "+f"(acc[mt][nt][2]), "+f"(acc[mt][nt][3])
                        : "r"(a[mt][0]), "r"(a[mt][1]), "r"(a[mt][2]), "r"(a[mt][3]),
                          "r"(b0), "r"(b1));
                }
        }
    }

    // Epilogue: masked max per row, straight from C fragments.
    int gid = lane >> 2, qid = lane & 3;
    int mat = colBase >> 12;
    #pragma unroll
    for (int mt = 0; mt < 2; mt++)
        #pragma unroll
        for (int half = 0; half < 2; half++) {
            int grow = rowBase + warpM * 32 + mt * 16 + half * 8 + gid;
            int rl   = labels[grow];
            float mx = -2.0f;
            #pragma unroll
            for (int nt = 0; nt < 8; nt++) {
                int c0 = warpN * 64 + nt * 8 + qid * 2;
                if (clab[c0]     != rl) mx = fmaxf(mx, acc[mt][nt][half * 2]);
                if (clab[c0 + 1] != rl) mx = fmaxf(mx, acc[mt][nt][half * 2 + 1]);
            }
            mx = fmaxf(mx, __shfl_xor_sync(0xffffffffu, mx, 1));
            mx = fmaxf(mx, __shfl_xor_sync(0xffffffffu, mx, 2));
            if (qid == 0)
                atomicMax(&g_maxkey[mat * BSZ + grow], enc_key(mx));
        }
}

// ============================================================================
// Kernel 3: deterministic finalize -> scalar mean loss
// ============================================================================
__global__ __launch_bounds__(1024) void finalize_kernel(float* __restrict__ out) {
    __shared__ float sm[32];
    float sum = 0.0f;
    for (int i = threadIdx.x; i < BSZ; i += 1024) {
        float daa = dec_key(g_maxkey[i]);
        #pragma unroll
        for (int v = 0; v < 2; v++) {
            float dap  = dec_key(g_maxkey[(1 + v) * BSZ + i]);
            float best = fmaxf(daa, dap);
            float neg  = sqrtf(fmaxf(2.0f - 2.0f * best, EPSQ));
            float pos  = sqrtf(fmaxf(2.0f - 2.0f * g_pos[v * BSZ + i], EPSQ));
            sum += fmaxf(pos - neg + MARGIN, 0.0f);
        }
    }
    #pragma unroll
    for (int o = 16; o; o >>= 1) sum += __shfl_down_sync(0xffffffffu, sum, o);
    int w = threadIdx.x >> 5, l = threadIdx.x & 31;
    if (l == 0) sm[w] = sum;
    __syncthreads();
    if (w == 0) {
        float t = sm[l];
        #pragma unroll
        for (int o = 16; o; o >>= 1) t += __shfl_down_sync(0xffffffffu, t, o);
        if (l == 0) out[0] = t / (2.0f * BSZ);
    }
}

// ============================================================================
extern "C" void kernel_launch(void* const* d_in, const int* in_sizes, int n_in,
                              void* d_out, int out_size) {
    const float* anchor   = (const float*)d_in[0];
    const float* positive = (const float*)d_in[1];
    const int*   labels   = (const int*)d_in[2];
    float*       out      = (float*)d_out;

    cudaFuncSetAttribute(gemm_max_mma,
                         cudaFuncAttributeMaxDynamicSharedMemorySize, SMEM_DYN);

    normalize_kernel<<<BSZ / 8, 256>>>(anchor, positive);
    gemm_max_mma<<<dim3(NF / BN, BSZ / BM), 512, SMEM_DYN>>>(labels);
    finalize_kernel<<<1, 1024>>>(out);
}

// round 15
// speedup vs baseline: 1.0682x; 1.0682x over previous
#include <cuda_runtime.h>
#include <cuda_bf16.h>
#include <cstdint>
#include <string.h>
#include <math.h>

#define BSZ 4096
#define DIM 256
#define NF  12288            // 3 * BSZ rows: [A ; P0 ; P1]
#define MARGIN 1.0f
#define EPSQ 1e-12f
#define ASTRIDE 40           // smem row stride in bf16 (80 B -> conflict-free ldmatrix)

#define BM 256
#define BN 128
#define ABYTES (BM * ASTRIDE * 2)      // 20480
#define BBYTES (BN * ASTRIDE * 2)      // 10240
#define STAGEBYTES (ABYTES + BBYTES)   // 30720
#define NSTAGE 3
#define SMEM_DYN (NSTAGE * STAGEBYTES + 512)

// ---------------- scratch (__device__ globals; no allocs allowed) -----------
__device__ __nv_bfloat16 g_Fh[NF * DIM];   // normalized rows, bf16 (GEMM)
__device__ float         g_pos[2 * BSZ];   // exact fp32 dot(a_i, p_{i,v})
__device__ unsigned      g_maxkey[3 * BSZ];

__device__ __forceinline__ uint32_t smem_to_u32(const void* p) {
    uint32_t a;
    asm("{ .reg .u64 t; cvta.to.shared.u64 t, %1; cvt.u32.u64 %0, t; }" : "=r"(a) : "l"(p));
    return a;
}
__device__ __forceinline__ void cp_async16(uint32_t saddr, const void* gaddr) {
    asm volatile("cp.async.ca.shared.global [%0], [%1], 16;"
                 :: "r"(saddr), "l"(gaddr) : "memory");
}
#define CP_COMMIT()  asm volatile("cp.async.commit_group;" ::: "memory")
#define CP_WAIT(n)   asm volatile("cp.async.wait_group %0;" :: "n"(n) : "memory")

// pack two floats -> bf16x2 bits
__device__ __forceinline__ uint32_t pack_bf16x2(float lo, float hi) {
    __nv_bfloat162 h = __floats2bfloat162_rn(lo, hi);
    uint32_t u;
    memcpy(&u, &h, 4);
    return u;
}

// ---- monotone float <-> uint encoding (atomicMax over signed floats) -------
__device__ __forceinline__ unsigned enc_key(float f) {
    unsigned b = __float_as_uint(f);
    return (b & 0x80000000u) ? ~b : (b | 0x80000000u);
}
__device__ __forceinline__ float dec_key(unsigned k) {
    unsigned b = (k & 0x80000000u) ? (k & 0x7fffffffu) : ~k;
    return __uint_as_float(b);
}

// ============================================================================
// Kernel 1: warp-per-row normalize (no block barriers).
// ============================================================================
__global__ __launch_bounds__(256) void normalize_kernel(
    const float* __restrict__ anchor, const float* __restrict__ positive) {
    int gw   = (blockIdx.x * 256 + threadIdx.x) >> 5;   // row 0..4095
    int lane = threadIdx.x & 31;

    const float4* a4 = (const float4*)(anchor + (size_t)gw * DIM);
    float4 a0 = a4[lane * 2], a1 = a4[lane * 2 + 1];
    float ss = a0.x*a0.x + a0.y*a0.y + a0.z*a0.z + a0.w*a0.w
             + a1.x*a1.x + a1.y*a1.y + a1.z*a1.z + a1.w*a1.w;
    #pragma unroll
    for (int o = 16; o; o >>= 1) ss += __shfl_xor_sync(0xffffffffu, ss, o);
    float inv = 1.0f / fmaxf(sqrtf(ss), 1e-12f);
    a0.x *= inv; a0.y *= inv; a0.z *= inv; a0.w *= inv;
    a1.x *= inv; a1.y *= inv; a1.z *= inv; a1.w *= inv;
    {
        uint4 o;
        o.x = pack_bf16x2(a0.x, a0.y);
        o.y = pack_bf16x2(a0.z, a0.w);
        o.z = pack_bf16x2(a1.x, a1.y);
        o.w = pack_bf16x2(a1.z, a1.w);
        ((uint4*)(g_Fh + (size_t)gw * DIM))[lane] = o;
    }

    #pragma unroll
    for (int v = 0; v < 2; v++) {
        const float4* p4 = (const float4*)(positive + ((size_t)gw * 2 + v) * DIM);
        float4 p0 = p4[lane * 2], p1 = p4[lane * 2 + 1];
        float ps = p0.x*p0.x + p0.y*p0.y + p0.z*p0.z + p0.w*p0.w
                 + p1.x*p1.x + p1.y*p1.y + p1.z*p1.z + p1.w*p1.w;
        #pragma unroll
        for (int o = 16; o; o >>= 1) ps += __shfl_xor_sync(0xffffffffu, ps, o);
        float pinv = 1.0f / fmaxf(sqrtf(ps), 1e-12f);
        p0.x *= pinv; p0.y *= pinv; p0.z *= pinv; p0.w *= pinv;
        p1.x *= pinv; p1.y *= pinv; p1.z *= pinv; p1.w *= pinv;
        uint4 o;
        o.x = pack_bf16x2(p0.x, p0.y);
        o.y = pack_bf16x2(p0.z, p0.w);
        o.z = pack_bf16x2(p1.x, p1.y);
        o.w = pack_bf16x2(p1.z, p1.w);
        ((uint4*)(g_Fh + ((size_t)(1 + v) * BSZ + gw) * DIM))[lane] = o;

        float pd = a0.x*p0.x + a0.y*p0.y + a0.z*p0.z + a0.w*p0.w
                 + a1.x*p1.x + a1.y*p1.y + a1.z*p1.z + a1.w*p1.w;
        #pragma unroll
        for (int o2 = 16; o2; o2 >>= 1) pd += __shfl_xor_sync(0xffffffffu, pd, o2);
        if (lane == 0) g_pos[v * BSZ + gw] = pd;
    }
    if (lane < 3) g_maxkey[lane * BSZ + gw] = enc_key(-2.0f);
}

// ============================================================================
// Kernel 2: bf16 mma GEMM, CTA tile 256x128, 256 threads (8 warps: 4M x 2N),
// warp tile 64x64 = 4x8 mma fragments. 3-stage cp.async pipeline, one barrier
// per k-iter, fused masked row-max epilogue.
// ============================================================================
__global__ __launch_bounds__(256) void gemm_max_mma(const int* __restrict__ labels) {
    extern __shared__ char dsm[];
    uint32_t sbase = smem_to_u32(dsm);
    int* clab = (int*)(dsm + NSTAGE * STAGEBYTES);

    int tid = threadIdx.x, lane = tid & 31, wid = tid >> 5;
    int rowBase = blockIdx.y * BM;     // [0, 4096)
    int colBase = blockIdx.x * BN;     // [0, 12288)
    if (tid < BN) clab[tid] = labels[(colBase & (BSZ - 1)) + tid];

    int warpM = wid & 3;               // 4 warps along M (64 rows each)
    int warpN = wid >> 2;              // 2 warps along N (64 cols each)

    // ldmatrix lane offsets (bytes, within one operand); += 32 B per k-step
    uint32_t offA[4], offB[4];
    #pragma unroll
    for (int mt = 0; mt < 4; mt++) {
        int r  = warpM * 64 + mt * 16 + (lane & 15);
        int kc = (lane >> 4) * 8;
        offA[mt] = (uint32_t)(r * ASTRIDE + kc) * 2u;
    }
    #pragma unroll
    for (int np = 0; np < 4; np++) {
        int n  = warpN * 64 + np * 16 + (lane & 7) + ((lane & 16) >> 1);
        int kc = ((lane >> 3) & 1) * 8;
        offB[np] = (uint32_t)(n * ASTRIDE + kc) * 2u;
    }

    float acc[4][8][4];
    #pragma unroll
    for (int mt = 0; mt < 4; mt++)
        #pragma unroll
        for (int nt = 0; nt < 8; nt++)
            #pragma unroll
            for (int c = 0; c < 4; c++) acc[mt][nt][c] = 0.0f;

    // Loader: 256 threads cover 64 rows x 32 bf16 per pass.
    int ldrow = tid >> 2, ldg = (tid & 3) * 8;
    const __nv_bfloat16* gA = g_Fh + (size_t)(rowBase + ldrow) * DIM + ldg;
    const __nv_bfloat16* gB = g_Fh + (size_t)(colBase + ldrow) * DIM + ldg;
    uint32_t srow = (uint32_t)(ldrow * ASTRIDE + ldg) * 2u;

    auto issue = [&](int stg, int kt) {
        uint32_t so = sbase + (uint32_t)stg * STAGEBYTES;
        #pragma unroll
        for (int p = 0; p < 4; p++)     // A: 4 passes of 64 rows
            cp_async16(so + (uint32_t)(p * 64 * ASTRIDE * 2) + srow,
                       gA + (size_t)p * 64 * DIM + kt);
        #pragma unroll
        for (int p = 0; p < 2; p++)     // B: 2 passes of 64 rows
            cp_async16(so + ABYTES + (uint32_t)(p * 64 * ASTRIDE * 2) + srow,
                       gB + (size_t)p * 64 * DIM + kt);
    };

    issue(0, 0);  CP_COMMIT();
    issue(1, 32); CP_COMMIT();

    #pragma unroll
    for (int i = 0; i < 8; i++) {
        if (i < 7) { CP_WAIT(1); } else { CP_WAIT(0); }
        __syncthreads();                  // stage i ready; stage (i+2)%3 free
        if (i < 6) { issue((i + 2) % NSTAGE, (i + 2) * 32); CP_COMMIT(); }

        uint32_t sa = sbase + (uint32_t)(i % NSTAGE) * STAGEBYTES;
        uint32_t sb = sa + ABYTES;
        #pragma unroll
        for (int ks = 0; ks < 2; ks++) {
            uint32_t a[4][4], b[4][4];
            #pragma unroll
            for (int mt = 0; mt < 4; mt++)
                asm volatile("ldmatrix.sync.aligned.m8n8.x4.shared.b16 "
                             "{%0,%1,%2,%3}, [%4];"
                             : "=r"(a[mt][0]), "=r"(a[mt][1]),
                               "=r"(a[mt][2]), "=r"(a[mt][3])
                             : "r"(sa + offA[mt] + ks * 32u));
            #pragma unroll
            for (int np = 0; np < 4; np++)
                asm volatile("ldmatrix.sync.aligned.m8n8.x4.shared.b16 "
                             "{%0,%1,%2,%3}, [%4];"
                             : "=r"(b[np][0]), "=r"(b[np][1]),
                               "=r"(b[np][2]), "=r"(b[np][3])
                             : "r"(sb + offB[np] + ks * 32u));
            #pragma unroll
            for (int mt = 0; mt < 4; mt++)
                #pragma unroll
                for (int nt = 0; nt < 8; nt++) {
                    uint32_t b0 = b[nt >> 1][(nt & 1) * 2];
                    uint32_t b1 = b[nt >> 1][(nt & 1) * 2 + 1];
                    asm volatile(
                        "mma.sync.aligned.m16n8k16.row.col.f32.bf16.bf16.f32 "
                        "{%0,%1,%2,%3}, {%4,%5,%6,%7}, {%8,%9}, {%0,%1,%2,%3};"
                        : "+f"(acc[mt][nt][0]), "+f"(acc[mt][nt][1]),
                          "+f"(acc[mt][nt][2]), "+f"(acc[mt][nt][3])
                        : "r"(a[mt][0]), "r"(a[mt][1]), "r"(a[mt][2]), "r"(a[mt][3]),
                          "r"(b0), "r"(b1));
                }
        }
    }

    // Epilogue: masked max per row, straight from C fragments.
    int gid = lane >> 2, qid = lane & 3;
    int mat = colBase >> 12;
    #pragma unroll
    for (int mt = 0; mt < 4; mt++)
        #pragma unroll
        for (int half = 0; half < 2; half++) {
            int grow = rowBase + warpM * 64 + mt * 16 + half * 8 + gid;
            int rl   = labels[grow];
            float mx = -2.0f;
            #pragma unroll
            for (int nt = 0; nt < 8; nt++) {
                int c0 = warpN * 64 + nt * 8 + qid * 2;
                if (clab[c0]     != rl) mx = fmaxf(mx, acc[mt][nt][half * 2]);
                if (clab[c0 + 1] != rl) mx = fmaxf(mx, acc[mt][nt][half * 2 + 1]);
            }
            mx = fmaxf(mx, __shfl_xor_sync(0xffffffffu, mx, 1));
            mx = fmaxf(mx, __shfl_xor_sync(0xffffffffu, mx, 2));
            if (qid == 0)
                atomicMax(&g_maxkey[mat * BSZ + grow], enc_key(mx));
        }
}

// ============================================================================
// Kernel 3: deterministic finalize -> scalar mean loss
// ============================================================================
__global__ __launch_bounds__(1024) void finalize_kernel(float* __restrict__ out) {
    __shared__ float sm[32];
    float sum = 0.0f;
    for (int i = threadIdx.x; i < BSZ; i += 1024) {
        float daa = dec_key(g_maxkey[i]);
        #pragma unroll
        for (int v = 0; v < 2; v++) {
            float dap  = dec_key(g_maxkey[(1 + v) * BSZ + i]);
            float best = fmaxf(daa, dap);
            float neg  = sqrtf(fmaxf(2.0f - 2.0f * best, EPSQ));
            float pos  = sqrtf(fmaxf(2.0f - 2.0f * g_pos[v * BSZ + i], EPSQ));
            sum += fmaxf(pos - neg + MARGIN, 0.0f);
        }
    }
    #pragma unroll
    for (int o = 16; o; o >>= 1) sum += __shfl_down_sync(0xffffffffu, sum, o);
    int w = threadIdx.x >> 5, l = threadIdx.x & 31;
    if (l == 0) sm[w] = sum;
    __syncthreads();
    if (w == 0) {
        float t = sm[l];
        #pragma unroll
        for (int o = 16; o; o >>= 1) t += __shfl_down_sync(0xffffffffu, t, o);
        if (l == 0) out[0] = t / (2.0f * BSZ);
    }
}

// ============================================================================
extern "C" void kernel_launch(void* const* d_in, const int* in_sizes, int n_in,
                              void* d_out, int out_size) {
    const float* anchor   = (const float*)d_in[0];
    const float* positive = (const float*)d_in[1];
    const int*   labels   = (const int*)d_in[2];
    float*       out      = (float*)d_out;

    cudaFuncSetAttribute(gemm_max_mma,
                         cudaFuncAttributeMaxDynamicSharedMemorySize, SMEM_DYN);

    normalize_kernel<<<BSZ / 8, 256>>>(anchor, positive);
    gemm_max_mma<<<dim3(NF / BN, BSZ / BM), 256, SMEM_DYN>>>(labels);
    finalize_kernel<<<1, 1024>>>(out);
}

// round 16
// speedup vs baseline: 1.2313x; 1.1527x over previous
#include <cuda_runtime.h>
#include <cuda_bf16.h>
#include <cstdint>
#include <string.h>
#include <math.h>

#define BSZ 4096
#define DIM 256
#define NF  12288            // 3 * BSZ rows: [A ; P0 ; P1]
#define MARGIN 1.0f
#define EPSQ 1e-12f
#define ASTRIDE 40           // smem row stride in bf16 (80 B -> conflict-free ldmatrix)
#define OPBYTES   (128 * ASTRIDE * 2)     // one operand, one stage: 10240 B
#define STAGEBYTES (2 * OPBYTES)          // A + B per stage: 20480 B
#define NSTAGE 3
#define SMEM_DYN (NSTAGE * STAGEBYTES + 512)   // + clab

// ---------------- scratch (__device__ globals; no allocs allowed) -----------
__device__ __nv_bfloat16 g_Fh[NF * DIM];   // normalized rows, bf16 (GEMM)
__device__ float         g_pos[2 * BSZ];   // exact fp32 dot(a_i, p_{i,v})
__device__ unsigned      g_maxkey[3 * BSZ];

__device__ __forceinline__ uint32_t smem_to_u32(const void* p) {
    uint32_t a;
    asm("{ .reg .u64 t; cvta.to.shared.u64 t, %1; cvt.u32.u64 %0, t; }" : "=r"(a) : "l"(p));
    return a;
}
__device__ __forceinline__ void cp_async16(uint32_t saddr, const void* gaddr) {
    asm volatile("cp.async.ca.shared.global [%0], [%1], 16;"
                 :: "r"(saddr), "l"(gaddr) : "memory");
}
#define CP_COMMIT()  asm volatile("cp.async.commit_group;" ::: "memory")
#define CP_WAIT(n)   asm volatile("cp.async.wait_group %0;" :: "n"(n) : "memory")

// pack two floats -> bf16x2 bits
__device__ __forceinline__ uint32_t pack_bf16x2(float lo, float hi) {
    __nv_bfloat162 h = __floats2bfloat162_rn(lo, hi);
    uint32_t u;
    memcpy(&u, &h, 4);
    return u;
}

// ---- monotone float <-> uint encoding (atomicMax over signed floats) -------
__device__ __forceinline__ unsigned enc_key(float f) {
    unsigned b = __float_as_uint(f);
    return (b & 0x80000000u) ? ~b : (b | 0x80000000u);
}
__device__ __forceinline__ float dec_key(unsigned k) {
    unsigned b = (k & 0x80000000u) ? (k & 0x7fffffffu) : ~k;
    return __uint_as_float(b);
}

// ============================================================================
// Kernel 1: warp-per-row normalize (no block barriers).
// ============================================================================
__global__ __launch_bounds__(256) void normalize_kernel(
    const float* __restrict__ anchor, const float* __restrict__ positive) {
    int gw   = (blockIdx.x * 256 + threadIdx.x) >> 5;   // row 0..4095
    int lane = threadIdx.x & 31;

    const float4* a4 = (const float4*)(anchor + (size_t)gw * DIM);
    float4 a0 = a4[lane * 2], a1 = a4[lane * 2 + 1];
    float ss = a0.x*a0.x + a0.y*a0.y + a0.z*a0.z + a0.w*a0.w
             + a1.x*a1.x + a1.y*a1.y + a1.z*a1.z + a1.w*a1.w;
    #pragma unroll
    for (int o = 16; o; o >>= 1) ss += __shfl_xor_sync(0xffffffffu, ss, o);
    float inv = 1.0f / fmaxf(sqrtf(ss), 1e-12f);
    a0.x *= inv; a0.y *= inv; a0.z *= inv; a0.w *= inv;
    a1.x *= inv; a1.y *= inv; a1.z *= inv; a1.w *= inv;
    {
        uint4 o;
        o.x = pack_bf16x2(a0.x, a0.y);
        o.y = pack_bf16x2(a0.z, a0.w);
        o.z = pack_bf16x2(a1.x, a1.y);
        o.w = pack_bf16x2(a1.z, a1.w);
        ((uint4*)(g_Fh + (size_t)gw * DIM))[lane] = o;
    }

    #pragma unroll
    for (int v = 0; v < 2; v++) {
        const float4* p4 = (const float4*)(positive + ((size_t)gw * 2 + v) * DIM);
        float4 p0 = p4[lane * 2], p1 = p4[lane * 2 + 1];
        float ps = p0.x*p0.x + p0.y*p0.y + p0.z*p0.z + p0.w*p0.w
                 + p1.x*p1.x + p1.y*p1.y + p1.z*p1.z + p1.w*p1.w;
        #pragma unroll
        for (int o = 16; o; o >>= 1) ps += __shfl_xor_sync(0xffffffffu, ps, o);
        float pinv = 1.0f / fmaxf(sqrtf(ps), 1e-12f);
        p0.x *= pinv; p0.y *= pinv; p0.z *= pinv; p0.w *= pinv;
        p1.x *= pinv; p1.y *= pinv; p1.z *= pinv; p1.w *= pinv;
        uint4 o;
        o.x = pack_bf16x2(p0.x, p0.y);
        o.y = pack_bf16x2(p0.z, p0.w);
        o.z = pack_bf16x2(p1.x, p1.y);
        o.w = pack_bf16x2(p1.z, p1.w);
        ((uint4*)(g_Fh + ((size_t)(1 + v) * BSZ + gw) * DIM))[lane] = o;

        float pd = a0.x*p0.x + a0.y*p0.y + a0.z*p0.z + a0.w*p0.w
                 + a1.x*p1.x + a1.y*p1.y + a1.z*p1.z + a1.w*p1.w;
        #pragma unroll
        for (int o2 = 16; o2; o2 >>= 1) pd += __shfl_xor_sync(0xffffffffu, pd, o2);
        if (lane == 0) g_pos[v * BSZ + gw] = pd;
    }
    if (lane < 3) g_maxkey[lane * BSZ + gw] = enc_key(-2.0f);
}

// ============================================================================
// Kernel 2: bf16 mma GEMM (128x128 tile, 3-stage cp.async) + symmetry:
//   mat0 (A.A^T) is symmetric -> skip strictly-lower tiles; upper off-diag
//   tiles contribute row-max AND col-max (masked values are symmetric).
// ============================================================================
__global__ __launch_bounds__(256) void gemm_max_mma(const int* __restrict__ labels) {
    int rowBase = blockIdx.y * 128;    // [0, 4096)
    int colBase = blockIdx.x * 128;    // [0, 12288)
    int mat     = colBase >> 12;       // 0: aa, 1: ap0, 2: ap1

    // symmetry: skip strictly-lower mat0 tiles
    if (mat == 0 && colBase < rowBase) return;
    bool sym = (mat == 0) && (colBase > rowBase);

    extern __shared__ char dsm[];
    uint32_t sbase = smem_to_u32(dsm);
    int* clab = (int*)(dsm + NSTAGE * STAGEBYTES);

    int tid = threadIdx.x, lane = tid & 31, wid = tid >> 5;
    if (tid < 128) clab[tid] = labels[(colBase & (BSZ - 1)) + tid];

    int warpM = wid & 3;               // 4 warps along M (32 rows each)
    int warpN = wid >> 2;              // 2 warps along N (64 cols each)

    uint32_t offA[2], offB[4];
    #pragma unroll
    for (int mt = 0; mt < 2; mt++) {
        int r  = warpM * 32 + mt * 16 + (lane & 15);
        int kc = (lane >> 4) * 8;
        offA[mt] = (uint32_t)(r * ASTRIDE + kc) * 2u;
    }
    #pragma unroll
    for (int np = 0; np < 4; np++) {
        int n  = warpN * 64 + np * 16 + (lane & 7) + ((lane & 16) >> 1);
        int kc = ((lane >> 3) & 1) * 8;
        offB[np] = (uint32_t)(n * ASTRIDE + kc) * 2u;
    }

    float acc[2][8][4];
    #pragma unroll
    for (int mt = 0; mt < 2; mt++)
        #pragma unroll
        for (int nt = 0; nt < 8; nt++)
            #pragma unroll
            for (int c = 0; c < 4; c++) acc[mt][nt][c] = 0.0f;

    int ldrow = tid >> 2, ldg = (tid & 3) * 8;
    const __nv_bfloat16* gA = g_Fh + (size_t)(rowBase + ldrow) * DIM + ldg;
    const __nv_bfloat16* gB = g_Fh + (size_t)(colBase + ldrow) * DIM + ldg;
    uint32_t srow = (uint32_t)(ldrow * ASTRIDE + ldg) * 2u;

    auto issue = [&](int stg, int kt) {
        uint32_t so = sbase + (uint32_t)stg * STAGEBYTES;
        #pragma unroll
        for (int p = 0; p < 2; p++) {
            uint32_t ro = (uint32_t)(p * 64 * ASTRIDE * 2) + srow;
            cp_async16(so + ro,           gA + (size_t)p * 64 * DIM + kt);
            cp_async16(so + OPBYTES + ro, gB + (size_t)p * 64 * DIM + kt);
        }
    };

    issue(0, 0);  CP_COMMIT();
    issue(1, 32); CP_COMMIT();

    #pragma unroll
    for (int i = 0; i < 8; i++) {
        if (i < 7) { CP_WAIT(1); } else { CP_WAIT(0); }
        __syncthreads();                       // stage i ready; stage (i+2)%3 free
        if (i < 6) { issue((i + 2) % NSTAGE, (i + 2) * 32); CP_COMMIT(); }

        uint32_t sa = sbase + (uint32_t)(i % NSTAGE) * STAGEBYTES;
        uint32_t sb = sa + OPBYTES;
        #pragma unroll
        for (int ks = 0; ks < 2; ks++) {
            uint32_t a[2][4], b[4][4];
            #pragma unroll
            for (int mt = 0; mt < 2; mt++)
                asm volatile("ldmatrix.sync.aligned.m8n8.x4.shared.b16 "
                             "{%0,%1,%2,%3}, [%4];"
                             : "=r"(a[mt][0]), "=r"(a[mt][1]),
                               "=r"(a[mt][2]), "=r"(a[mt][3])
                             : "r"(sa + offA[mt] + ks * 32u));
            #pragma unroll
            for (int np = 0; np < 4; np++)
                asm volatile("ldmatrix.sync.aligned.m8n8.x4.shared.b16 "
                             "{%0,%1,%2,%3}, [%4];"
                             : "=r"(b[np][0]), "=r"(b[np][1]),
                               "=r"(b[np][2]), "=r"(b[np][3])
                             : "r"(sb + offB[np] + ks * 32u));
            #pragma unroll
            for (int mt = 0; mt < 2; mt++)
                #pragma unroll
                for (int nt = 0; nt < 8; nt++) {
                    uint32_t b0 = b[nt >> 1][(nt & 1) * 2];
                    uint32_t b1 = b[nt >> 1][(nt & 1) * 2 + 1];
                    asm volatile(
                        "mma.sync.aligned.m16n8k16.row.col.f32.bf16.bf16.f32 "
                        "{%0,%1,%2,%3}, {%4,%5,%6,%7}, {%8,%9}, {%0,%1,%2,%3};"
                        : "+f"(acc[mt][nt][0]), "+f"(acc[mt][nt][1]),
                          "+f"(acc[mt][nt][2]), "+f"(acc[mt][nt][3])
                        : "r"(a[mt][0]), "r"(a[mt][1]), "r"(a[mt][2]), "r"(a[mt][3]),
                          "r"(b0), "r"(b1));
                }
        }
    }

    // ---- Epilogue ----
    // Pass 1: mask values in place (-2 sentinel), fused row-max.
    int gid = lane >> 2, qid = lane & 3;
    #pragma unroll
    for (int mt = 0; mt < 2; mt++)
        #pragma unroll
        for (int half = 0; half < 2; half++) {
            int grow = rowBase + warpM * 32 + mt * 16 + half * 8 + gid;
            int rl   = labels[grow];
            float mx = -2.0f;
            #pragma unroll
            for (int nt = 0; nt < 8; nt++) {
                int c0 = warpN * 64 + nt * 8 + qid * 2;
                float v0 = (clab[c0]     != rl) ? acc[mt][nt][half * 2]     : -2.0f;
                float v1 = (clab[c0 + 1] != rl) ? acc[mt][nt][half * 2 + 1] : -2.0f;
                acc[mt][nt][half * 2]     = v0;
                acc[mt][nt][half * 2 + 1] = v1;
                mx = fmaxf(mx, fmaxf(v0, v1));
            }
            mx = fmaxf(mx, __shfl_xor_sync(0xffffffffu, mx, 1));
            mx = fmaxf(mx, __shfl_xor_sync(0xffffffffu, mx, 2));
            if (qid == 0)
                atomicMax(&g_maxkey[mat * BSZ + grow], enc_key(mx));
        }

    // Pass 2 (symmetric off-diagonal mat0 tiles): column-max -> row colBase+c.
    // C[r][c] == C[c][r] and the label mask is symmetric, so the masked value
    // also feeds row (colBase+c)'s max.
    if (sym) {
        #pragma unroll
        for (int nt = 0; nt < 8; nt++) {
            float c0m = -2.0f, c1m = -2.0f;
            #pragma unroll
            for (int mt = 0; mt < 2; mt++) {
                c0m = fmaxf(c0m, fmaxf(acc[mt][nt][0], acc[mt][nt][2]));
                c1m = fmaxf(c1m, fmaxf(acc[mt][nt][1], acc[mt][nt][3]));
            }
            #pragma unroll
            for (int o = 4; o <= 16; o <<= 1) {
                c0m = fmaxf(c0m, __shfl_xor_sync(0xffffffffu, c0m, o));
                c1m = fmaxf(c1m, __shfl_xor_sync(0xffffffffu, c1m, o));
            }
            if (gid == 0) {                      // lanes 0..3, qid = lane
                int c0 = colBase + warpN * 64 + nt * 8 + qid * 2;
                atomicMax(&g_maxkey[c0],     enc_key(c0m));
                atomicMax(&g_maxkey[c0 + 1], enc_key(c1m));
            }
        }
    }
}

// ============================================================================
// Kernel 3: deterministic finalize -> scalar mean loss
// ============================================================================
__global__ __launch_bounds__(1024) void finalize_kernel(float* __restrict__ out) {
    __shared__ float sm[32];
    float sum = 0.0f;
    for (int i = threadIdx.x; i < BSZ; i += 1024) {
        float daa = dec_key(g_maxkey[i]);
        #pragma unroll
        for (int v = 0; v < 2; v++) {
            float dap  = dec_key(g_maxkey[(1 + v) * BSZ + i]);
            float best = fmaxf(daa, dap);
            float neg  = sqrtf(fmaxf(2.0f - 2.0f * best, EPSQ));
            float pos  = sqrtf(fmaxf(2.0f - 2.0f * g_pos[v * BSZ + i], EPSQ));
            sum += fmaxf(pos - neg + MARGIN, 0.0f);
        }
    }
    #pragma unroll
    for (int o = 16; o; o >>= 1) sum += __shfl_down_sync(0xffffffffu, sum, o);
    int w = threadIdx.x >> 5, l = threadIdx.x & 31;
    if (l == 0) sm[w] = sum;
    __syncthreads();
    if (w == 0) {
        float t = sm[l];
        #pragma unroll
        for (int o = 16; o; o >>= 1) t += __shfl_down_sync(0xffffffffu, t, o);
        if (l == 0) out[0] = t / (2.0f * BSZ);
    }
}

// ============================================================================
extern "C" void kernel_launch(void* const* d_in, const int* in_sizes, int n_in,
                              void* d_out, int out_size) {
    const float* anchor   = (const float*)d_in[0];
    const float* positive = (const float*)d_in[1];
    const int*   labels   = (const int*)d_in[2];
    float*       out      = (float*)d_out;

    cudaFuncSetAttribute(gemm_max_mma,
                         cudaFuncAttributeMaxDynamicSharedMemorySize, SMEM_DYN);

    normalize_kernel<<<BSZ / 8, 256>>>(anchor, positive);
    gemm_max_mma<<<dim3(NF / 128, BSZ / 128), 256, SMEM_DYN>>>(labels);
    finalize_kernel<<<1, 1024>>>(out);
}